// round 1
// baseline (speedup 1.0000x reference)
#include <cuda_runtime.h>
#include <math.h>

#define DM   1024
#define NH   16
#define HD   64
#define BB   4
#define TT   2048
#define MT   (BB * TT)        // 8192 rows

// Scratch (allocation rules: __device__ globals only)
__device__ float g_Q[(size_t)MT * DM];
__device__ float g_K[(size_t)MT * DM];
__device__ float g_V[(size_t)MT * DM];
__device__ float g_C[(size_t)MT * DM];

// ---------------------------------------------------------------------------
// GEMM: C[m][n] = sum_k A[m][k] * W[n][k] + bias[n]   (A: MxK row-major,
// W: NxK row-major, i.e. y = A @ W^T + b — torch Linear convention)
// MODE 0: write out[m*DM + n]           (plain (B,T,D))
// MODE 1: write head-split (B,H,T,hd):  out[((b*NH+h)*TT + t)*HD + d]
// 128x128 tile, BK=16, 256 threads, 8x8 micro-tile per thread.
// ---------------------------------------------------------------------------
template <int MODE>
__global__ __launch_bounds__(256) void gemm_kernel(
    const float* __restrict__ A, const float* __restrict__ W,
    const float* __restrict__ bias, float* __restrict__ out)
{
    __shared__ float As[16][132];
    __shared__ float Bs[16][132];

    const int tid = threadIdx.x;
    const int bm  = blockIdx.y * 128;
    const int bn  = blockIdx.x * 128;
    const int tx  = tid & 15;      // 0..15 -> N micro
    const int ty  = tid >> 4;      // 0..15 -> M micro
    const int lr  = tid >> 2;      // 0..63 loader row
    const int lk  = (tid & 3) << 2; // 0,4,8,12 loader k (float4)

    float acc[8][8];
#pragma unroll
    for (int i = 0; i < 8; i++)
#pragma unroll
        for (int j = 0; j < 8; j++) acc[i][j] = 0.f;

    for (int k0 = 0; k0 < DM; k0 += 16) {
        float4 a0 = *(const float4*)(A + (size_t)(bm + lr)      * DM + k0 + lk);
        float4 a1 = *(const float4*)(A + (size_t)(bm + lr + 64) * DM + k0 + lk);
        float4 b0 = *(const float4*)(W + (size_t)(bn + lr)      * DM + k0 + lk);
        float4 b1 = *(const float4*)(W + (size_t)(bn + lr + 64) * DM + k0 + lk);

        __syncthreads();   // previous iteration's compute done reading smem
        As[lk + 0][lr]      = a0.x; As[lk + 1][lr]      = a0.y;
        As[lk + 2][lr]      = a0.z; As[lk + 3][lr]      = a0.w;
        As[lk + 0][lr + 64] = a1.x; As[lk + 1][lr + 64] = a1.y;
        As[lk + 2][lr + 64] = a1.z; As[lk + 3][lr + 64] = a1.w;
        Bs[lk + 0][lr]      = b0.x; Bs[lk + 1][lr]      = b0.y;
        Bs[lk + 2][lr]      = b0.z; Bs[lk + 3][lr]      = b0.w;
        Bs[lk + 0][lr + 64] = b1.x; Bs[lk + 1][lr + 64] = b1.y;
        Bs[lk + 2][lr + 64] = b1.z; Bs[lk + 3][lr + 64] = b1.w;
        __syncthreads();

#pragma unroll
        for (int k = 0; k < 16; k++) {
            float a[8], b[8];
            *(float4*)(a)     = *(const float4*)&As[k][ty * 8];
            *(float4*)(a + 4) = *(const float4*)&As[k][ty * 8 + 4];
            *(float4*)(b)     = *(const float4*)&Bs[k][tx * 8];
            *(float4*)(b + 4) = *(const float4*)&Bs[k][tx * 8 + 4];
#pragma unroll
            for (int i = 0; i < 8; i++)
#pragma unroll
                for (int j = 0; j < 8; j++)
                    acc[i][j] = fmaf(a[i], b[j], acc[i][j]);
        }
    }

    // Epilogue
#pragma unroll
    for (int i = 0; i < 8; i++) {
        const int m = bm + ty * 8 + i;
        const int bidx = m / TT;
        const int t    = m % TT;
#pragma unroll
        for (int j = 0; j < 8; j++) {
            const int n = bn + tx * 8 + j;
            const float v = acc[i][j] + bias[n];
            if (MODE == 0) {
                out[(size_t)m * DM + n] = v;
            } else {
                const int h = n >> 6;
                const int d = n & 63;
                out[((size_t)(bidx * NH + h) * TT + t) * HD + d] = v;
            }
        }
    }
}

// ---------------------------------------------------------------------------
// Causal flash attention, fp32. One block = one (b,h, 64-query tile).
// 256 threads: thread owns row r = tid/4, 16 columns c = (tid&3)*16 + i.
// Online softmax; P staged through smem for the PV product.
// Writes ctx directly in (B,T,D) layout for the O projection.
// ---------------------------------------------------------------------------
#define PADW 65
#define ATT_SMEM (4 * 64 * PADW * (int)sizeof(float))   // 66560 B

__global__ __launch_bounds__(256) void attn_kernel()
{
    extern __shared__ float sm[];
    float* Qs = sm;                  // [64][65]
    float* Ks = sm + 64 * PADW;      // [64][65]
    float* Vs = sm + 2 * 64 * PADW;  // [64][65]
    float* Ps = sm + 3 * 64 * PADW;  // [64][65]

    const int tid = threadIdx.x;
    const int r   = tid >> 2;        // query row within tile (0..63)
    const int cg  = tid & 3;
    const int c0  = cg * 16;

    const int qt = blockIdx.x;       // query tile (0..31)
    const int h  = blockIdx.y;
    const int b  = blockIdx.z;
    const size_t base = (size_t)(b * NH + h) * TT * HD;
    const int q0 = qt * 64;

    // Load Q tile
#pragma unroll
    for (int u = 0; u < 4; u++) {
        float4 v = *(const float4*)(g_Q + base + (size_t)(q0 + r) * HD + c0 + u * 4);
        Qs[r * PADW + c0 + u * 4 + 0] = v.x;
        Qs[r * PADW + c0 + u * 4 + 1] = v.y;
        Qs[r * PADW + c0 + u * 4 + 2] = v.z;
        Qs[r * PADW + c0 + u * 4 + 3] = v.w;
    }

    float m_i = -1e30f, l_i = 0.f;
    float acc[16];
#pragma unroll
    for (int i = 0; i < 16; i++) acc[i] = 0.f;

    for (int j = 0; j <= qt; j++) {
        // Prefetch K/V tile to registers
        float4 kr[4], vr[4];
#pragma unroll
        for (int u = 0; u < 4; u++) {
            kr[u] = *(const float4*)(g_K + base + (size_t)(j * 64 + r) * HD + c0 + u * 4);
            vr[u] = *(const float4*)(g_V + base + (size_t)(j * 64 + r) * HD + c0 + u * 4);
        }
        __syncthreads();   // previous PV done reading Vs/Ps (and Qs ready on j==0)
#pragma unroll
        for (int u = 0; u < 4; u++) {
            Ks[r * PADW + c0 + u * 4 + 0] = kr[u].x;
            Ks[r * PADW + c0 + u * 4 + 1] = kr[u].y;
            Ks[r * PADW + c0 + u * 4 + 2] = kr[u].z;
            Ks[r * PADW + c0 + u * 4 + 3] = kr[u].w;
            Vs[r * PADW + c0 + u * 4 + 0] = vr[u].x;
            Vs[r * PADW + c0 + u * 4 + 1] = vr[u].y;
            Vs[r * PADW + c0 + u * 4 + 2] = vr[u].z;
            Vs[r * PADW + c0 + u * 4 + 3] = vr[u].w;
        }
        __syncthreads();

        // S = Q @ K^T (16 cols per thread)
        float s[16];
#pragma unroll
        for (int i = 0; i < 16; i++) s[i] = 0.f;
#pragma unroll 16
        for (int d = 0; d < 64; d++) {
            const float q = Qs[r * PADW + d];
#pragma unroll
            for (int i = 0; i < 16; i++)
                s[i] = fmaf(q, Ks[(c0 + i) * PADW + d], s[i]);
        }

        const int kbase = j * 64;
#pragma unroll
        for (int i = 0; i < 16; i++) {
            s[i] *= 0.125f;                                   // 1/sqrt(64)
            if (kbase + c0 + i > q0 + r) s[i] = -1e30f;       // causal
        }

        // Online softmax (4 threads per row cooperate via shfl)
        float mloc = s[0];
#pragma unroll
        for (int i = 1; i < 16; i++) mloc = fmaxf(mloc, s[i]);
        mloc = fmaxf(mloc, __shfl_xor_sync(0xffffffffu, mloc, 1));
        mloc = fmaxf(mloc, __shfl_xor_sync(0xffffffffu, mloc, 2));
        const float m_new = fmaxf(m_i, mloc);

        float psum = 0.f;
#pragma unroll
        for (int i = 0; i < 16; i++) {
            s[i] = __expf(s[i] - m_new);
            psum += s[i];
            Ps[r * PADW + c0 + i] = s[i];
        }
        psum += __shfl_xor_sync(0xffffffffu, psum, 1);
        psum += __shfl_xor_sync(0xffffffffu, psum, 2);

        const float corr = __expf(m_i - m_new);
        l_i = l_i * corr + psum;
        m_i = m_new;
#pragma unroll
        for (int i = 0; i < 16; i++) acc[i] *= corr;

        __syncthreads();   // Ps visible to whole row

        // O += P @ V
#pragma unroll 8
        for (int k = 0; k < 64; k++) {
            const float p = Ps[r * PADW + k];
#pragma unroll
            for (int i = 0; i < 16; i++)
                acc[i] = fmaf(p, Vs[k * PADW + c0 + i], acc[i]);
        }
    }

    // Normalize + write ctx in (B,T,D) layout
    const float inv = 1.f / l_i;
    const size_t o = ((size_t)(b * TT + q0 + r)) * DM + h * HD + c0;
#pragma unroll
    for (int u = 0; u < 4; u++) {
        float4 v = make_float4(acc[u * 4 + 0] * inv, acc[u * 4 + 1] * inv,
                               acc[u * 4 + 2] * inv, acc[u * 4 + 3] * inv);
        *(float4*)(g_C + o + u * 4) = v;
    }
}

// ---------------------------------------------------------------------------
extern "C" void kernel_launch(void* const* d_in, const int* in_sizes, int n_in,
                              void* d_out, int out_size)
{
    const float* x  = (const float*)d_in[0];
    const float* Wq = (const float*)d_in[1];
    const float* bq = (const float*)d_in[2];
    const float* Wk = (const float*)d_in[3];
    const float* bk = (const float*)d_in[4];
    const float* Wv = (const float*)d_in[5];
    const float* bv = (const float*)d_in[6];
    const float* Wo = (const float*)d_in[7];
    const float* bo = (const float*)d_in[8];
    float* out = (float*)d_out;

    float *Qp, *Kp, *Vp, *Cp;
    cudaGetSymbolAddress((void**)&Qp, g_Q);
    cudaGetSymbolAddress((void**)&Kp, g_K);
    cudaGetSymbolAddress((void**)&Vp, g_V);
    cudaGetSymbolAddress((void**)&Cp, g_C);

    cudaFuncSetAttribute(attn_kernel,
                         cudaFuncAttributeMaxDynamicSharedMemorySize, ATT_SMEM);

    dim3 ggrid(DM / 128, MT / 128);   // (8, 64)
    gemm_kernel<1><<<ggrid, 256>>>(x, Wq, bq, Qp);
    gemm_kernel<1><<<ggrid, 256>>>(x, Wk, bk, Kp);
    gemm_kernel<1><<<ggrid, 256>>>(x, Wv, bv, Vp);

    dim3 agrid(TT / 64, NH, BB);      // (32, 16, 4)
    attn_kernel<<<agrid, 256, ATT_SMEM>>>();

    gemm_kernel<0><<<ggrid, 256>>>(Cp, Wo, bo, out);
}